// round 8
// baseline (speedup 1.0000x reference)
#include <cuda_runtime.h>
#include <math.h>

// Problem constants (from reference)
#define BATCH       64
#define NUM_HEADS   32
#define HEAD_DIM    128
#define KVH         8
#define G           4       // query heads per kv head
#define BS          16      // tokens per KV block
#define MAXB        128     // max blocks per sequence
#define LMAX        2048    // MAXB * BS
#define QK_SCALE    0.08838834764831845f
#define NTHREADS    256
#define NWARPS      (NTHREADS / 32)

__global__ __launch_bounds__(NTHREADS) void paged_attn_kernel(
    const float* __restrict__ q,            // [B, H, D]
    const float* __restrict__ k_cache,      // [NB, BS, KVH, D]
    const float* __restrict__ v_cache,      // [NB, BS, KVH, D]
    const int*   __restrict__ block_tables, // [B, MAXB]
    const int*   __restrict__ context_lens, // [B]
    float*       __restrict__ out)          // [B, H, D]
{
    __shared__ float sq[G * HEAD_DIM];      // 2 KB: 4 query rows
    __shared__ float slog[G][LMAX];         // 32 KB: logits -> probs -> (reused) partial accs
    __shared__ int   sbt[MAXB];             // block table
    __shared__ float swr[2][G][NWARPS];     // cross-warp reduce scratch (max, sum)

    const int b    = blockIdx.y;
    const int kvh  = blockIdx.x;
    const int tid  = threadIdx.x;
    const int lane = tid & 31;
    const int warp = tid >> 5;

    const int ctx  = __ldg(&context_lens[b]);
    const int nblk = (ctx + BS - 1) / BS;

    for (int i = tid; i < nblk; i += NTHREADS)
        sbt[i] = block_tables[b * MAXB + i];
    for (int i = tid; i < G * HEAD_DIM; i += NTHREADS)
        sq[i] = q[(size_t)(b * NUM_HEADS + kvh * G) * HEAD_DIM + i];
    __syncthreads();

    // ---------------- Phase 1: QK logits (thread-per-token) ----------------
    float lmax0 = -1e30f, lmax1 = -1e30f, lmax2 = -1e30f, lmax3 = -1e30f;

    const float4* sq0 = reinterpret_cast<const float4*>(sq);
    const float4* sq1 = reinterpret_cast<const float4*>(sq + HEAD_DIM);
    const float4* sq2 = reinterpret_cast<const float4*>(sq + 2 * HEAD_DIM);
    const float4* sq3 = reinterpret_cast<const float4*>(sq + 3 * HEAD_DIM);

    for (int t = tid; t < ctx; t += NTHREADS) {
        const int blk = sbt[t >> 4];
        const float4* krow = reinterpret_cast<const float4*>(
            k_cache + ((((size_t)blk * BS + (t & 15)) * KVH + kvh) * HEAD_DIM));
        float a0 = 0.f, a1 = 0.f, a2 = 0.f, a3 = 0.f;
        #pragma unroll 8
        for (int i = 0; i < HEAD_DIM / 4; i++) {
            const float4 kv = krow[i];
            const float4 q0 = sq0[i];
            const float4 q1 = sq1[i];
            const float4 q2 = sq2[i];
            const float4 q3 = sq3[i];
            a0 += q0.x * kv.x + q0.y * kv.y + q0.z * kv.z + q0.w * kv.w;
            a1 += q1.x * kv.x + q1.y * kv.y + q1.z * kv.z + q1.w * kv.w;
            a2 += q2.x * kv.x + q2.y * kv.y + q2.z * kv.z + q2.w * kv.w;
            a3 += q3.x * kv.x + q3.y * kv.y + q3.z * kv.z + q3.w * kv.w;
        }
        a0 *= QK_SCALE; a1 *= QK_SCALE; a2 *= QK_SCALE; a3 *= QK_SCALE;
        slog[0][t] = a0; lmax0 = fmaxf(lmax0, a0);
        slog[1][t] = a1; lmax1 = fmaxf(lmax1, a1);
        slog[2][t] = a2; lmax2 = fmaxf(lmax2, a2);
        slog[3][t] = a3; lmax3 = fmaxf(lmax3, a3);
    }

    // block-reduce max per head
    {
        float m[G] = {lmax0, lmax1, lmax2, lmax3};
        #pragma unroll
        for (int h = 0; h < G; h++) {
            float v = m[h];
            #pragma unroll
            for (int off = 16; off; off >>= 1)
                v = fmaxf(v, __shfl_xor_sync(0xffffffffu, v, off));
            if (lane == 0) swr[0][h][warp] = v;
        }
    }
    __syncthreads();
    float gmax[G];
    #pragma unroll
    for (int h = 0; h < G; h++) {
        float v = -1e30f;
        #pragma unroll
        for (int w = 0; w < NWARPS; w++) v = fmaxf(v, swr[0][h][w]);
        gmax[h] = v;
    }

    // exp pass + sum (probs written back to slog, unnormalized)
    float lsum[G] = {0.f, 0.f, 0.f, 0.f};
    for (int t = tid; t < ctx; t += NTHREADS) {
        #pragma unroll
        for (int h = 0; h < G; h++) {
            float p = __expf(slog[h][t] - gmax[h]);
            slog[h][t] = p;
            lsum[h] += p;
        }
    }
    #pragma unroll
    for (int h = 0; h < G; h++) {
        float v = lsum[h];
        #pragma unroll
        for (int off = 16; off; off >>= 1)
            v += __shfl_xor_sync(0xffffffffu, v, off);
        if (lane == 0) swr[1][h][warp] = v;
    }
    __syncthreads();
    float ginv[G];
    #pragma unroll
    for (int h = 0; h < G; h++) {
        float v = 0.f;
        #pragma unroll
        for (int w = 0; w < NWARPS; w++) v += swr[1][h][w];
        ginv[h] = 1.0f / v;
    }

    // ---------------- Phase 2: PV (warp-per-token-stripe, lane owns float4 of D) ----------------
    // Each V row is read exactly once, coalesced (32 lanes x 16B = 512B row).
    const int d4 = lane;                 // float4 index in D
    float4 acc[G];
    #pragma unroll
    for (int h = 0; h < G; h++) acc[h] = make_float4(0.f, 0.f, 0.f, 0.f);

    for (int t = warp; t < ctx; t += NWARPS) {
        const int blk = sbt[t >> 4];
        const float4* vrow = reinterpret_cast<const float4*>(
            v_cache + ((((size_t)blk * BS + (t & 15)) * KVH + kvh) * HEAD_DIM));
        const float4 vv = vrow[d4];
        #pragma unroll
        for (int h = 0; h < G; h++) {
            const float p = slog[h][t];   // smem broadcast within warp
            acc[h].x += p * vv.x;
            acc[h].y += p * vv.y;
            acc[h].z += p * vv.z;
            acc[h].w += p * vv.w;
        }
    }

    // cross-warp reduction of partial accumulators; reuse slog as scratch.
    __syncthreads();   // all slog reads done
    float* sacc = &slog[0][0];           // [NWARPS][G][HEAD_DIM] = 16 KB, fits in 32 KB
    #pragma unroll
    for (int h = 0; h < G; h++) {
        float4* dst = reinterpret_cast<float4*>(sacc + ((warp * G + h) * HEAD_DIM));
        dst[d4] = acc[h];
    }
    __syncthreads();

    if (tid < G * 32) {
        const int h  = tid >> 5;
        const int dd = tid & 31;
        float4 s = make_float4(0.f, 0.f, 0.f, 0.f);
        #pragma unroll
        for (int w = 0; w < NWARPS; w++) {
            const float4 p = reinterpret_cast<const float4*>(
                sacc + ((w * G + h) * HEAD_DIM))[dd];
            s.x += p.x; s.y += p.y; s.z += p.z; s.w += p.w;
        }
        const float inv = ginv[h];
        s.x *= inv; s.y *= inv; s.z *= inv; s.w *= inv;
        float4* orow = reinterpret_cast<float4*>(
            out + (size_t)(b * NUM_HEADS + kvh * G + h) * HEAD_DIM);
        orow[dd] = s;
    }
}

extern "C" void kernel_launch(void* const* d_in, const int* in_sizes, int n_in,
                              void* d_out, int out_size) {
    const float* q            = (const float*)d_in[0];
    const float* k_cache      = (const float*)d_in[1];
    const float* v_cache      = (const float*)d_in[2];
    const int*   block_tables = (const int*)d_in[3];
    const int*   context_lens = (const int*)d_in[4];
    float* out = (float*)d_out;

    dim3 grid(KVH, BATCH);   // (kv_head, batch)
    paged_attn_kernel<<<grid, NTHREADS>>>(q, k_cache, v_cache,
                                          block_tables, context_lens, out);
}

// round 9
// speedup vs baseline: 1.7279x; 1.7279x over previous
#include <cuda_runtime.h>
#include <math.h>

// Problem constants (from reference)
#define BATCH       64
#define NUM_HEADS   32
#define HEAD_DIM    128
#define KVH         8
#define G           4       // query heads per kv head
#define BS          16      // tokens per KV block
#define MAXB        128     // max blocks per sequence
#define LMAX        2048    // MAXB * BS
#define QK_SCALE    0.08838834764831845f

// Split-K (flash-decode) parameters
#define CHUNK       256                 // tokens per partition
#define NPART       (LMAX / CHUNK)      // 8
#define CBLKS       (CHUNK / BS)        // 16 KV blocks per partition

#define NTHREADS    256
#define NWARPS      (NTHREADS / 32)

// Scratch for partial results (no allocation allowed -> __device__ globals)
// layout: [B*KVH][NPART][G][HEAD_DIM]
__device__ float g_pout[BATCH * KVH * NPART * G * HEAD_DIM];   // 8 MB
__device__ float g_pm[BATCH * KVH * NPART * G];                // chunk max
__device__ float g_pl[BATCH * KVH * NPART * G];                // chunk expsum

// ---------------------------------------------------------------------------
// Kernel 1: per-(b, kvh, partition) local attention over <=256 tokens.
// Writes unnormalized acc = sum_t exp(logit_t - m) * v_t, plus (m, l).
// ---------------------------------------------------------------------------
__global__ __launch_bounds__(NTHREADS) void pa_partial_kernel(
    const float* __restrict__ q,            // [B, H, D]
    const float* __restrict__ k_cache,      // [NB, BS, KVH, D]
    const float* __restrict__ v_cache,      // [NB, BS, KVH, D]
    const int*   __restrict__ block_tables, // [B, MAXB]
    const int*   __restrict__ context_lens) // [B]
{
    const int kvh = blockIdx.x;
    const int b   = blockIdx.y;
    const int p   = blockIdx.z;

    const int ctx = __ldg(&context_lens[b]);
    const int t0  = p * CHUNK;
    if (t0 >= ctx) return;                    // inactive partition
    const int nt  = min(ctx - t0, CHUNK);

    __shared__ float sq[G * HEAD_DIM];        // 2 KB
    __shared__ float slog[G][CHUNK];          // 4 KB (probs)
    __shared__ float sacc[NWARPS][G][HEAD_DIM]; // 16 KB partial accumulators
    __shared__ int   sbt[CBLKS];
    __shared__ float swr[2][G][NWARPS];

    const int tid  = threadIdx.x;
    const int lane = tid & 31;
    const int warp = tid >> 5;

    const int nblk = (nt + BS - 1) / BS;
    if (tid < nblk)
        sbt[tid] = block_tables[b * MAXB + (t0 >> 4) + tid];
    for (int i = tid; i < G * HEAD_DIM; i += NTHREADS)
        sq[i] = q[(size_t)(b * NUM_HEADS + kvh * G) * HEAD_DIM + i];
    __syncthreads();

    const float4* sq0 = reinterpret_cast<const float4*>(sq);
    const float4* sq1 = reinterpret_cast<const float4*>(sq + HEAD_DIM);
    const float4* sq2 = reinterpret_cast<const float4*>(sq + 2 * HEAD_DIM);
    const float4* sq3 = reinterpret_cast<const float4*>(sq + 3 * HEAD_DIM);

    // ---- Phase 1: QK logits, one token per thread ----
    const int t   = tid;                      // chunk-local token
    const bool act = (t < nt);
    float a0 = -1e30f, a1 = -1e30f, a2 = -1e30f, a3 = -1e30f;
    if (act) {
        const int blk = sbt[t >> 4];
        const float4* krow = reinterpret_cast<const float4*>(
            k_cache + ((((size_t)blk * BS + (t & 15)) * KVH + kvh) * HEAD_DIM));
        float s0 = 0.f, s1 = 0.f, s2 = 0.f, s3 = 0.f;
        #pragma unroll 8
        for (int i = 0; i < HEAD_DIM / 4; i++) {
            const float4 kv = krow[i];
            const float4 q0 = sq0[i];
            const float4 q1 = sq1[i];
            const float4 q2 = sq2[i];
            const float4 q3 = sq3[i];
            s0 += q0.x * kv.x + q0.y * kv.y + q0.z * kv.z + q0.w * kv.w;
            s1 += q1.x * kv.x + q1.y * kv.y + q1.z * kv.z + q1.w * kv.w;
            s2 += q2.x * kv.x + q2.y * kv.y + q2.z * kv.z + q2.w * kv.w;
            s3 += q3.x * kv.x + q3.y * kv.y + q3.z * kv.z + q3.w * kv.w;
        }
        a0 = s0 * QK_SCALE; a1 = s1 * QK_SCALE;
        a2 = s2 * QK_SCALE; a3 = s3 * QK_SCALE;
    }

    // block max per head
    {
        float m[G] = {a0, a1, a2, a3};
        #pragma unroll
        for (int h = 0; h < G; h++) {
            float v = m[h];
            #pragma unroll
            for (int off = 16; off; off >>= 1)
                v = fmaxf(v, __shfl_xor_sync(0xffffffffu, v, off));
            if (lane == 0) swr[0][h][warp] = v;
        }
    }
    __syncthreads();
    float gmax[G];
    #pragma unroll
    for (int h = 0; h < G; h++) {
        float v = -1e30f;
        #pragma unroll
        for (int w = 0; w < NWARPS; w++) v = fmaxf(v, swr[0][h][w]);
        gmax[h] = v;
    }

    // exp + block sum; probs to slog
    float pv[G] = {0.f, 0.f, 0.f, 0.f};
    if (act) {
        pv[0] = __expf(a0 - gmax[0]);
        pv[1] = __expf(a1 - gmax[1]);
        pv[2] = __expf(a2 - gmax[2]);
        pv[3] = __expf(a3 - gmax[3]);
        slog[0][t] = pv[0]; slog[1][t] = pv[1];
        slog[2][t] = pv[2]; slog[3][t] = pv[3];
    }
    #pragma unroll
    for (int h = 0; h < G; h++) {
        float v = pv[h];
        #pragma unroll
        for (int off = 16; off; off >>= 1)
            v += __shfl_xor_sync(0xffffffffu, v, off);
        if (lane == 0) swr[1][h][warp] = v;
    }
    __syncthreads();

    // ---- Phase 2: PV, warp-per-token stripe, lane owns float4 of D ----
    const int d4 = lane;
    float4 acc[G];
    #pragma unroll
    for (int h = 0; h < G; h++) acc[h] = make_float4(0.f, 0.f, 0.f, 0.f);

    for (int tt = warp; tt < nt; tt += NWARPS) {
        const int blk = sbt[tt >> 4];
        const float4* vrow = reinterpret_cast<const float4*>(
            v_cache + ((((size_t)blk * BS + (tt & 15)) * KVH + kvh) * HEAD_DIM));
        const float4 vv = vrow[d4];
        #pragma unroll
        for (int h = 0; h < G; h++) {
            const float pp = slog[h][tt];
            acc[h].x += pp * vv.x;
            acc[h].y += pp * vv.y;
            acc[h].z += pp * vv.z;
            acc[h].w += pp * vv.w;
        }
    }
    #pragma unroll
    for (int h = 0; h < G; h++)
        reinterpret_cast<float4*>(sacc[warp][h])[d4] = acc[h];
    __syncthreads();

    // combine warps + write partials
    const size_t base = ((size_t)(b * KVH + kvh) * NPART + p) * G;
    if (tid < G * 32) {
        const int h  = tid >> 5;
        const int dd = tid & 31;
        float4 s = make_float4(0.f, 0.f, 0.f, 0.f);
        #pragma unroll
        for (int w = 0; w < NWARPS; w++) {
            const float4 x = reinterpret_cast<const float4*>(sacc[w][h])[dd];
            s.x += x.x; s.y += x.y; s.z += x.z; s.w += x.w;
        }
        reinterpret_cast<float4*>(g_pout + (base + h) * HEAD_DIM)[dd] = s;
    }
    if (tid < G) {
        float L = 0.f;
        #pragma unroll
        for (int w = 0; w < NWARPS; w++) L += swr[1][tid][w];
        g_pm[base + tid] = gmax[tid];
        g_pl[base + tid] = L;
    }
}

// ---------------------------------------------------------------------------
// Kernel 2: log-sum-exp combine across partitions.
// grid = B*KVH blocks, 128 threads: thread = (g, d4).
// ---------------------------------------------------------------------------
__global__ __launch_bounds__(G * 32) void pa_reduce_kernel(
    const int* __restrict__ context_lens,
    float*     __restrict__ out)            // [B, H, D]
{
    const int bk  = blockIdx.x;             // b*KVH + kvh
    const int b   = bk / KVH;
    const int kvh = bk % KVH;
    const int tid = threadIdx.x;
    const int g   = tid >> 5;
    const int d4  = tid & 31;

    const int ctx = __ldg(&context_lens[b]);
    const int np  = (ctx + CHUNK - 1) / CHUNK;

    const size_t base = (size_t)bk * NPART * G;

    float M = -1e30f;
    for (int p = 0; p < np; p++)
        M = fmaxf(M, g_pm[base + p * G + g]);

    float L = 0.f;
    float4 acc = make_float4(0.f, 0.f, 0.f, 0.f);
    for (int p = 0; p < np; p++) {
        const size_t idx = base + p * G + g;
        const float s = __expf(g_pm[idx] - M);
        L += g_pl[idx] * s;
        const float4 a = reinterpret_cast<const float4*>(
            g_pout + idx * HEAD_DIM)[d4];
        acc.x += a.x * s; acc.y += a.y * s;
        acc.z += a.z * s; acc.w += a.w * s;
    }

    const float inv = 1.0f / L;
    float4* orow = reinterpret_cast<float4*>(
        out + (size_t)(b * NUM_HEADS + kvh * G + g) * HEAD_DIM);
    orow[d4] = make_float4(acc.x * inv, acc.y * inv, acc.z * inv, acc.w * inv);
}

extern "C" void kernel_launch(void* const* d_in, const int* in_sizes, int n_in,
                              void* d_out, int out_size) {
    const float* q            = (const float*)d_in[0];
    const float* k_cache      = (const float*)d_in[1];
    const float* v_cache      = (const float*)d_in[2];
    const int*   block_tables = (const int*)d_in[3];
    const int*   context_lens = (const int*)d_in[4];
    float* out = (float*)d_out;

    dim3 grid1(KVH, BATCH, NPART);
    pa_partial_kernel<<<grid1, NTHREADS>>>(q, k_cache, v_cache,
                                           block_tables, context_lens);
    pa_reduce_kernel<<<BATCH * KVH, G * 32>>>(context_lens, out);
}

// round 10
// speedup vs baseline: 1.7937x; 1.0380x over previous
#include <cuda_runtime.h>
#include <math.h>

// Problem constants (from reference)
#define BATCH       64
#define NUM_HEADS   32
#define HEAD_DIM    128
#define KVH         8
#define G           4       // query heads per kv head
#define BS          16      // tokens per KV block
#define MAXB        128     // max blocks per sequence
#define LMAX        2048    // MAXB * BS
#define QK_SCALE    0.08838834764831845f

// Split-K (flash-decode) parameters
#define CHUNK       128                 // tokens per partition
#define NPART       (LMAX / CHUNK)      // 16
#define CBLKS       (CHUNK / BS)        // 8 KV blocks per partition

#define NTHREADS    128
#define NWARPS      (NTHREADS / 32)     // 4

// Scratch for partial results (no allocation allowed -> __device__ globals)
// layout: [B*KVH][NPART][G][HEAD_DIM]
__device__ float g_pout[BATCH * KVH * NPART * G * HEAD_DIM];   // 16.8 MB
__device__ float g_pm[BATCH * KVH * NPART * G];                // chunk max
__device__ float g_pl[BATCH * KVH * NPART * G];                // chunk expsum

// ---------------------------------------------------------------------------
// Kernel 1: per-(b, kvh, partition) local attention over <=128 tokens.
// Writes unnormalized acc = sum_t exp(logit_t - m) * v_t, plus (m, l).
// ---------------------------------------------------------------------------
__global__ __launch_bounds__(NTHREADS) void pa_partial_kernel(
    const float* __restrict__ q,            // [B, H, D]
    const float* __restrict__ k_cache,      // [NB, BS, KVH, D]
    const float* __restrict__ v_cache,      // [NB, BS, KVH, D]
    const int*   __restrict__ block_tables, // [B, MAXB]
    const int*   __restrict__ context_lens) // [B]
{
    const int kvh = blockIdx.x;
    const int b   = blockIdx.y;
    const int p   = blockIdx.z;

    const int ctx = __ldg(&context_lens[b]);
    const int t0  = p * CHUNK;
    if (t0 >= ctx) return;                    // inactive partition
    const int nt  = min(ctx - t0, CHUNK);

    __shared__ float sq[G * HEAD_DIM];          // 2 KB
    __shared__ float slog[G][CHUNK];            // 2 KB (probs)
    __shared__ float sacc[NWARPS][G][HEAD_DIM]; // 8 KB partial accumulators
    __shared__ int   sbt[CBLKS];
    __shared__ float swr[2][G][NWARPS];

    const int tid  = threadIdx.x;
    const int lane = tid & 31;
    const int warp = tid >> 5;

    const int nblk = (nt + BS - 1) / BS;
    if (tid < nblk)
        sbt[tid] = block_tables[b * MAXB + (t0 >> 4) + tid];
    #pragma unroll
    for (int i = tid; i < G * HEAD_DIM; i += NTHREADS)
        sq[i] = q[(size_t)(b * NUM_HEADS + kvh * G) * HEAD_DIM + i];
    __syncthreads();

    const float4* sq0 = reinterpret_cast<const float4*>(sq);
    const float4* sq1 = reinterpret_cast<const float4*>(sq + HEAD_DIM);
    const float4* sq2 = reinterpret_cast<const float4*>(sq + 2 * HEAD_DIM);
    const float4* sq3 = reinterpret_cast<const float4*>(sq + 3 * HEAD_DIM);

    // ---- Phase 1: QK logits, one token per thread ----
    const int t    = tid;                     // chunk-local token
    const bool act = (t < nt);
    float a0 = -1e30f, a1 = -1e30f, a2 = -1e30f, a3 = -1e30f;
    if (act) {
        const int blk = sbt[t >> 4];
        const float4* krow = reinterpret_cast<const float4*>(
            k_cache + ((((size_t)blk * BS + (t & 15)) * KVH + kvh) * HEAD_DIM));
        float s0 = 0.f, s1 = 0.f, s2 = 0.f, s3 = 0.f;
        #pragma unroll 8
        for (int i = 0; i < HEAD_DIM / 4; i++) {
            const float4 kv = krow[i];
            const float4 q0 = sq0[i];
            const float4 q1 = sq1[i];
            const float4 q2 = sq2[i];
            const float4 q3 = sq3[i];
            s0 += q0.x * kv.x + q0.y * kv.y + q0.z * kv.z + q0.w * kv.w;
            s1 += q1.x * kv.x + q1.y * kv.y + q1.z * kv.z + q1.w * kv.w;
            s2 += q2.x * kv.x + q2.y * kv.y + q2.z * kv.z + q2.w * kv.w;
            s3 += q3.x * kv.x + q3.y * kv.y + q3.z * kv.z + q3.w * kv.w;
        }
        a0 = s0 * QK_SCALE; a1 = s1 * QK_SCALE;
        a2 = s2 * QK_SCALE; a3 = s3 * QK_SCALE;
    }

    // block max per head
    {
        float m[G] = {a0, a1, a2, a3};
        #pragma unroll
        for (int h = 0; h < G; h++) {
            float v = m[h];
            #pragma unroll
            for (int off = 16; off; off >>= 1)
                v = fmaxf(v, __shfl_xor_sync(0xffffffffu, v, off));
            if (lane == 0) swr[0][h][warp] = v;
        }
    }
    __syncthreads();
    float gmax[G];
    #pragma unroll
    for (int h = 0; h < G; h++) {
        float v = -1e30f;
        #pragma unroll
        for (int w = 0; w < NWARPS; w++) v = fmaxf(v, swr[0][h][w]);
        gmax[h] = v;
    }

    // exp + block sum; probs to slog
    float pv[G] = {0.f, 0.f, 0.f, 0.f};
    if (act) {
        pv[0] = __expf(a0 - gmax[0]);
        pv[1] = __expf(a1 - gmax[1]);
        pv[2] = __expf(a2 - gmax[2]);
        pv[3] = __expf(a3 - gmax[3]);
        slog[0][t] = pv[0]; slog[1][t] = pv[1];
        slog[2][t] = pv[2]; slog[3][t] = pv[3];
    }
    #pragma unroll
    for (int h = 0; h < G; h++) {
        float v = pv[h];
        #pragma unroll
        for (int off = 16; off; off >>= 1)
            v += __shfl_xor_sync(0xffffffffu, v, off);
        if (lane == 0) swr[1][h][warp] = v;
    }
    __syncthreads();

    // ---- Phase 2: PV, warp-per-token stripe, lane owns float4 of D ----
    const int d4 = lane;
    float4 acc[G];
    #pragma unroll
    for (int h = 0; h < G; h++) acc[h] = make_float4(0.f, 0.f, 0.f, 0.f);

    for (int tt = warp; tt < nt; tt += NWARPS) {
        const int blk = sbt[tt >> 4];
        const float4* vrow = reinterpret_cast<const float4*>(
            v_cache + ((((size_t)blk * BS + (tt & 15)) * KVH + kvh) * HEAD_DIM));
        const float4 vv = vrow[d4];
        #pragma unroll
        for (int h = 0; h < G; h++) {
            const float pp = slog[h][tt];
            acc[h].x += pp * vv.x;
            acc[h].y += pp * vv.y;
            acc[h].z += pp * vv.z;
            acc[h].w += pp * vv.w;
        }
    }
    #pragma unroll
    for (int h = 0; h < G; h++)
        reinterpret_cast<float4*>(sacc[warp][h])[d4] = acc[h];
    __syncthreads();

    // combine warps + write partials
    const size_t base = ((size_t)(b * KVH + kvh) * NPART + p) * G;
    {
        const int h  = tid >> 5;                // 128 threads = G*32 exactly
        const int dd = tid & 31;
        float4 s = make_float4(0.f, 0.f, 0.f, 0.f);
        #pragma unroll
        for (int w = 0; w < NWARPS; w++) {
            const float4 x = reinterpret_cast<const float4*>(sacc[w][h])[dd];
            s.x += x.x; s.y += x.y; s.z += x.z; s.w += x.w;
        }
        reinterpret_cast<float4*>(g_pout + (base + h) * HEAD_DIM)[dd] = s;
    }
    if (tid < G) {
        float L = 0.f;
        #pragma unroll
        for (int w = 0; w < NWARPS; w++) L += swr[1][tid][w];
        g_pm[base + tid] = gmax[tid];
        g_pl[base + tid] = L;
    }
}

// ---------------------------------------------------------------------------
// Kernel 2: log-sum-exp combine across partitions.
// grid = B*KVH blocks, 128 threads: thread = (g, d4).
// ---------------------------------------------------------------------------
__global__ __launch_bounds__(G * 32) void pa_reduce_kernel(
    const int* __restrict__ context_lens,
    float*     __restrict__ out)            // [B, H, D]
{
    const int bk  = blockIdx.x;             // b*KVH + kvh
    const int b   = bk / KVH;
    const int kvh = bk % KVH;
    const int tid = threadIdx.x;
    const int g   = tid >> 5;
    const int d4  = tid & 31;

    const int ctx = __ldg(&context_lens[b]);
    const int np  = (ctx + CHUNK - 1) / CHUNK;

    const size_t base = (size_t)bk * NPART * G;

    float M = -1e30f;
    for (int p = 0; p < np; p++)
        M = fmaxf(M, g_pm[base + p * G + g]);

    float L = 0.f;
    float4 acc = make_float4(0.f, 0.f, 0.f, 0.f);
    for (int p = 0; p < np; p++) {
        const size_t idx = base + p * G + g;
        const float s = __expf(g_pm[idx] - M);
        L += g_pl[idx] * s;
        const float4 a = reinterpret_cast<const float4*>(
            g_pout + idx * HEAD_DIM)[d4];
        acc.x += a.x * s; acc.y += a.y * s;
        acc.z += a.z * s; acc.w += a.w * s;
    }

    const float inv = 1.0f / L;
    float4* orow = reinterpret_cast<float4*>(
        out + (size_t)(b * NUM_HEADS + kvh * G + g) * HEAD_DIM);
    orow[d4] = make_float4(acc.x * inv, acc.y * inv, acc.z * inv, acc.w * inv);
}

extern "C" void kernel_launch(void* const* d_in, const int* in_sizes, int n_in,
                              void* d_out, int out_size) {
    const float* q            = (const float*)d_in[0];
    const float* k_cache      = (const float*)d_in[1];
    const float* v_cache      = (const float*)d_in[2];
    const int*   block_tables = (const int*)d_in[3];
    const int*   context_lens = (const int*)d_in[4];
    float* out = (float*)d_out;

    dim3 grid1(KVH, BATCH, NPART);
    pa_partial_kernel<<<grid1, NTHREADS>>>(q, k_cache, v_cache,
                                           block_tables, context_lens);
    pa_reduce_kernel<<<BATCH * KVH, G * 32>>>(context_lens, out);
}

// round 11
// speedup vs baseline: 1.8165x; 1.0128x over previous
#include <cuda_runtime.h>
#include <math.h>

// Problem constants (from reference)
#define BATCH       64
#define NUM_HEADS   32
#define HEAD_DIM    128
#define KVH         8
#define G           4       // query heads per kv head
#define BS          16      // tokens per KV block
#define MAXB        128     // max blocks per sequence
#define LMAX        2048    // MAXB * BS
#define QK_SCALE    0.08838834764831845f

// Split-K (flash-decode) parameters
#define CHUNK       128                 // tokens per partition
#define NPART       (LMAX / CHUNK)      // 16
#define CBLKS       (CHUNK / BS)        // 8 KV blocks per partition

#define NTHREADS    128
#define NWARPS      (NTHREADS / 32)     // 4

// Scratch for partial results (no allocation allowed -> __device__ globals)
// layout: [B*KVH][NPART][G][HEAD_DIM]
__device__ float g_pout[BATCH * KVH * NPART * G * HEAD_DIM];   // 16.8 MB
__device__ float g_pm[BATCH * KVH * NPART * G];                // chunk max
__device__ float g_pl[BATCH * KVH * NPART * G];                // chunk expsum

// ---------------------------------------------------------------------------
// Kernel 1: per-(b, kvh, partition) local attention over <=128 tokens.
// Phase 1 is warp-per-token / lane-owns-d4: one coalesced LDG.128 per K row
// (4 L1tex wavefronts instead of 32), shuffle-reduced dot products.
// ---------------------------------------------------------------------------
__global__ __launch_bounds__(NTHREADS) void pa_partial_kernel(
    const float* __restrict__ q,            // [B, H, D]
    const float* __restrict__ k_cache,      // [NB, BS, KVH, D]
    const float* __restrict__ v_cache,      // [NB, BS, KVH, D]
    const int*   __restrict__ block_tables, // [B, MAXB]
    const int*   __restrict__ context_lens) // [B]
{
    const int kvh = blockIdx.x;
    const int b   = blockIdx.y;
    const int p   = blockIdx.z;

    const int ctx = __ldg(&context_lens[b]);
    const int t0  = p * CHUNK;
    if (t0 >= ctx) return;                    // inactive partition
    const int nt  = min(ctx - t0, CHUNK);

    __shared__ float slog[G][CHUNK];            // 2 KB: logits -> probs
    __shared__ float sacc[NWARPS][G][HEAD_DIM]; // 8 KB partial accumulators
    __shared__ int   sbt[CBLKS];
    __shared__ float swr[2][G][NWARPS];

    const int tid  = threadIdx.x;
    const int lane = tid & 31;
    const int warp = tid >> 5;

    const int nblk = (nt + BS - 1) / BS;
    if (tid < nblk)
        sbt[tid] = block_tables[b * MAXB + (t0 >> 4) + tid];
    __syncthreads();

    // Q rows held in registers: lane owns float4 d4=lane of each head.
    float4 qreg[G];
    #pragma unroll
    for (int h = 0; h < G; h++)
        qreg[h] = reinterpret_cast<const float4*>(
            q + (size_t)(b * NUM_HEADS + kvh * G + h) * HEAD_DIM)[lane];

    // ---- Phase 1: QK logits (warp-per-token, lane = d4) ----
    float lmax[G] = {-1e30f, -1e30f, -1e30f, -1e30f};

    for (int tt = warp; tt < nt; tt += NWARPS) {
        const int blk = sbt[tt >> 4];
        const float4 kv = reinterpret_cast<const float4*>(
            k_cache + ((((size_t)blk * BS + (tt & 15)) * KVH + kvh) * HEAD_DIM))[lane];
        float s[G];
        #pragma unroll
        for (int h = 0; h < G; h++) {
            float v = qreg[h].x * kv.x + qreg[h].y * kv.y
                    + qreg[h].z * kv.z + qreg[h].w * kv.w;
            #pragma unroll
            for (int off = 16; off; off >>= 1)
                v += __shfl_xor_sync(0xffffffffu, v, off);
            s[h] = v * QK_SCALE;                // all lanes hold the full sum
        }
        #pragma unroll
        for (int h = 0; h < G; h++) {
            lmax[h] = fmaxf(lmax[h], s[h]);
            if (lane == h) slog[h][tt] = s[h];  // one lane writes per head
        }
    }
    if (lane == 0) {
        #pragma unroll
        for (int h = 0; h < G; h++) swr[0][h][warp] = lmax[h];
    }
    __syncthreads();

    float gmax[G];
    #pragma unroll
    for (int h = 0; h < G; h++) {
        float v = -1e30f;
        #pragma unroll
        for (int w = 0; w < NWARPS; w++) v = fmaxf(v, swr[0][h][w]);
        gmax[h] = v;
    }

    // exp pass (thread-per-token) + block expsum
    float pv[G] = {0.f, 0.f, 0.f, 0.f};
    if (tid < nt) {
        #pragma unroll
        for (int h = 0; h < G; h++) {
            float pp = __expf(slog[h][tid] - gmax[h]);
            slog[h][tid] = pp;
            pv[h] = pp;
        }
    }
    #pragma unroll
    for (int h = 0; h < G; h++) {
        float v = pv[h];
        #pragma unroll
        for (int off = 16; off; off >>= 1)
            v += __shfl_xor_sync(0xffffffffu, v, off);
        if (lane == 0) swr[1][h][warp] = v;
    }
    __syncthreads();   // probs visible for phase 2

    // ---- Phase 2: PV (warp-per-token, lane = d4), 2-way unrolled ----
    const int d4 = lane;
    float4 acc[G];
    #pragma unroll
    for (int h = 0; h < G; h++) acc[h] = make_float4(0.f, 0.f, 0.f, 0.f);

    int tt = warp;
    for (; tt + NWARPS < nt; tt += 2 * NWARPS) {
        const int ta = tt, tb = tt + NWARPS;
        const int blka = sbt[ta >> 4];
        const int blkb = sbt[tb >> 4];
        const float4 va = reinterpret_cast<const float4*>(
            v_cache + ((((size_t)blka * BS + (ta & 15)) * KVH + kvh) * HEAD_DIM))[d4];
        const float4 vb = reinterpret_cast<const float4*>(
            v_cache + ((((size_t)blkb * BS + (tb & 15)) * KVH + kvh) * HEAD_DIM))[d4];
        #pragma unroll
        for (int h = 0; h < G; h++) {
            const float pa = slog[h][ta];
            const float pb = slog[h][tb];
            acc[h].x += pa * va.x + pb * vb.x;
            acc[h].y += pa * va.y + pb * vb.y;
            acc[h].z += pa * va.z + pb * vb.z;
            acc[h].w += pa * va.w + pb * vb.w;
        }
    }
    for (; tt < nt; tt += NWARPS) {
        const int blk = sbt[tt >> 4];
        const float4 vv = reinterpret_cast<const float4*>(
            v_cache + ((((size_t)blk * BS + (tt & 15)) * KVH + kvh) * HEAD_DIM))[d4];
        #pragma unroll
        for (int h = 0; h < G; h++) {
            const float pp = slog[h][tt];
            acc[h].x += pp * vv.x;
            acc[h].y += pp * vv.y;
            acc[h].z += pp * vv.z;
            acc[h].w += pp * vv.w;
        }
    }
    #pragma unroll
    for (int h = 0; h < G; h++)
        reinterpret_cast<float4*>(sacc[warp][h])[d4] = acc[h];
    __syncthreads();

    // combine warps + write partials
    const size_t base = ((size_t)(b * KVH + kvh) * NPART + p) * G;
    {
        const int h  = tid >> 5;                // 128 threads = G*32 exactly
        const int dd = tid & 31;
        float4 s = make_float4(0.f, 0.f, 0.f, 0.f);
        #pragma unroll
        for (int w = 0; w < NWARPS; w++) {
            const float4 x = reinterpret_cast<const float4*>(sacc[w][h])[dd];
            s.x += x.x; s.y += x.y; s.z += x.z; s.w += x.w;
        }
        reinterpret_cast<float4*>(g_pout + (base + h) * HEAD_DIM)[dd] = s;
    }
    if (tid < G) {
        float L = 0.f;
        #pragma unroll
        for (int w = 0; w < NWARPS; w++) L += swr[1][tid][w];
        g_pm[base + tid] = gmax[tid];
        g_pl[base + tid] = L;
    }
}

// ---------------------------------------------------------------------------
// Kernel 2: log-sum-exp combine. One block per (b, kvh, g); partitions split
// across 4 warps, lane = d4, smem combine. grid = 2048, block = 128.
// ---------------------------------------------------------------------------
__global__ __launch_bounds__(NTHREADS) void pa_reduce_kernel(
    const int* __restrict__ context_lens,
    float*     __restrict__ out)            // [B, H, D]
{
    const int bkg = blockIdx.x;             // (b*KVH + kvh)*G + g
    const int bk  = bkg >> 2;
    const int g   = bkg & 3;
    const int b   = bk / KVH;
    const int kvh = bk % KVH;
    const int tid = threadIdx.x;
    const int pp  = tid >> 5;               // warp id = partition stripe
    const int d4  = tid & 31;

    const int ctx = __ldg(&context_lens[b]);
    const int np  = (ctx + CHUNK - 1) / CHUNK;

    __shared__ float  sm[NPART];
    __shared__ float  sl[NPART];
    __shared__ float4 sred[NWARPS][32];

    const size_t base = (size_t)bk * NPART * G;

    if (tid < np) {
        sm[tid] = g_pm[base + tid * G + g];
        sl[tid] = g_pl[base + tid * G + g];
    }
    __syncthreads();

    float M = -1e30f;
    for (int pi = 0; pi < np; pi++) M = fmaxf(M, sm[pi]);
    float L = 0.f;
    for (int pi = 0; pi < np; pi++) L += sl[pi] * __expf(sm[pi] - M);

    float4 acc = make_float4(0.f, 0.f, 0.f, 0.f);
    for (int pi = pp; pi < np; pi += NWARPS) {
        const float s = __expf(sm[pi] - M);
        const float4 a = reinterpret_cast<const float4*>(
            g_pout + (base + pi * G + g) * HEAD_DIM)[d4];
        acc.x += a.x * s; acc.y += a.y * s;
        acc.z += a.z * s; acc.w += a.w * s;
    }
    sred[pp][d4] = acc;
    __syncthreads();

    if (tid < 32) {
        float4 s = make_float4(0.f, 0.f, 0.f, 0.f);
        #pragma unroll
        for (int w = 0; w < NWARPS; w++) {
            const float4 x = sred[w][tid];
            s.x += x.x; s.y += x.y; s.z += x.z; s.w += x.w;
        }
        const float inv = 1.0f / L;
        float4* orow = reinterpret_cast<float4*>(
            out + (size_t)(b * NUM_HEADS + kvh * G + g) * HEAD_DIM);
        orow[tid] = make_float4(s.x * inv, s.y * inv, s.z * inv, s.w * inv);
    }
}

extern "C" void kernel_launch(void* const* d_in, const int* in_sizes, int n_in,
                              void* d_out, int out_size) {
    const float* q            = (const float*)d_in[0];
    const float* k_cache      = (const float*)d_in[1];
    const float* v_cache      = (const float*)d_in[2];
    const int*   block_tables = (const int*)d_in[3];
    const int*   context_lens = (const int*)d_in[4];
    float* out = (float*)d_out;

    dim3 grid1(KVH, BATCH, NPART);
    pa_partial_kernel<<<grid1, NTHREADS>>>(q, k_cache, v_cache,
                                           block_tables, context_lens);
    pa_reduce_kernel<<<BATCH * KVH * G, NTHREADS>>>(context_lens, out);
}